// round 16
// baseline (speedup 1.0000x reference)
#include <cuda_runtime.h>
#include <cuda_bf16.h>
#include <cuda_fp8.h>
#include <cstdint>

// fp8(e4m3) mma.sync m16n8k32 fused MoE-PINN — (tile,expert) grid,
// pair-grouped commits, 6-slot ring, transposed [N][K] fp8 weights.

__device__ __nv_fp8_e4m3 g_We1t[6 * 1024 * 512];   // [e][n][k]
__device__ __nv_fp8_e4m3 g_We2t[6 * 512 * 1024];   // [e][n][k]
__device__ float g_routing[32768 * 6];
__device__ float g_wacc[32768 * 3];

__device__ __forceinline__ float fast_tanh(float x) {
    float e = __expf(2.0f * x);
    return 1.0f - __fdividef(2.0f, e + 1.0f);
}
__device__ __forceinline__ uint32_t smem_u32(const void* p) {
    return (uint32_t)__cvta_generic_to_shared(p);
}
__device__ __forceinline__ void ldsm_x4(uint32_t (&r)[4], uint32_t a) {
    asm volatile("ldmatrix.sync.aligned.m8n8.x4.shared.b16 {%0,%1,%2,%3}, [%4];"
        : "=r"(r[0]), "=r"(r[1]), "=r"(r[2]), "=r"(r[3]) : "r"(a));
}
__device__ __forceinline__ void mma_fp8(float (&d)[4], const uint32_t (&a)[4],
                                        uint32_t b0, uint32_t b1) {
    asm volatile(
        "mma.sync.aligned.m16n8k32.row.col.f32.e4m3.e4m3.f32 "
        "{%0,%1,%2,%3}, {%4,%5,%6,%7}, {%8,%9}, {%0,%1,%2,%3};"
        : "+f"(d[0]), "+f"(d[1]), "+f"(d[2]), "+f"(d[3])
        : "r"(a[0]), "r"(a[1]), "r"(a[2]), "r"(a[3]), "r"(b0), "r"(b1));
}
__device__ __forceinline__ void cp16(uint32_t dst, const void* src) {
    asm volatile("cp.async.cg.shared.global [%0], [%1], 16;" :: "r"(dst), "l"(src));
}
__device__ __forceinline__ void cp_commit() { asm volatile("cp.async.commit_group;"); }
__device__ __forceinline__ void cp_wait0() { asm volatile("cp.async.wait_group 0;"); }
__device__ __forceinline__ void cp_wait1() { asm volatile("cp.async.wait_group 1;"); }

// ---------------- prep: transpose + fp8 convert weights ----------------
__global__ __launch_bounds__(256) void transpose_kernel(
    const float* __restrict__ src, __nv_fp8_e4m3* __restrict__ dst, int K, int N)
{
    __shared__ float tile[32][33];
    int e = blockIdx.z, k0 = blockIdx.x * 32, n0 = blockIdx.y * 32;
    const float* s = src + ((size_t)e * K + k0) * N + n0;
    for (int i = threadIdx.y; i < 32; i += 8)
        tile[i][threadIdx.x] = s[(size_t)i * N + threadIdx.x];
    __syncthreads();
    __nv_fp8_e4m3* d = dst + ((size_t)e * N + n0) * K + k0;
    for (int i = threadIdx.y; i < 32; i += 8)
        d[(size_t)i * K + threadIdx.x] = __nv_fp8_e4m3(tile[threadIdx.x][i]);
}

// ---------------- routing kernel (fp32; also zeros g_wacc) ----------------
__global__ __launch_bounds__(256, 1) void routing_kernel(
    const float* __restrict__ x,
    const float* __restrict__ Wr1, const float* __restrict__ br1,
    const float* __restrict__ Wr2, const float* __restrict__ br2)
{
    extern __shared__ char smraw[];
    float* xs = (float*)smraw;
    float* w1 = xs + 64 * 512;
    float* r1 = w1 + 512 * 32;
    float* w2 = r1 + 64 * 32;
    float* b1 = w2 + 192;
    float* b2 = b1 + 32;
    const int s = blockIdx.y, b0 = blockIdx.x * 64, tid = threadIdx.x;

    {
        int gidx = (blockIdx.y * 64 + blockIdx.x) * 256 + tid;
        if (gidx < 32768 * 3) g_wacc[gidx] = 0.f;
    }
    for (int i = tid; i < 64 * 512 / 4; i += 256) {
        int row = i >> 7, c4 = i & 127;
        ((float4*)xs)[i] = *(const float4*)(x + (size_t)(b0 + row) * 4096 + s * 512 + c4 * 4);
    }
    const float* w1g = Wr1 + (size_t)s * 512 * 32;
    for (int i = tid; i < 512 * 32 / 4; i += 256)
        ((float4*)w1)[i] = ((const float4*)w1g)[i];
    if (tid < 32)  b1[tid] = br1[s * 32 + tid];
    if (tid < 192) w2[tid] = Wr2[s * 192 + tid];
    if (tid < 6)   b2[tid] = br2[s * 6 + tid];
    __syncthreads();
    {
        int h = tid & 31, rg = tid >> 5;
        float acc[8];
#pragma unroll
        for (int r = 0; r < 8; ++r) acc[r] = 0.f;
        for (int k = 0; k < 512; ++k) {
            float w = w1[k * 32 + h];
#pragma unroll
            for (int r = 0; r < 8; ++r)
                acc[r] = fmaf(xs[(rg * 8 + r) * 512 + k], w, acc[r]);
        }
#pragma unroll
        for (int r = 0; r < 8; ++r)
            r1[(rg * 8 + r) * 32 + h] = fmaxf(acc[r] + b1[h], 0.f);
    }
    __syncthreads();
    if (tid < 64) {
        float lg[6];
#pragma unroll
        for (int e = 0; e < 6; ++e) lg[e] = b2[e];
        for (int h = 0; h < 32; ++h) {
            float rv = r1[tid * 32 + h];
#pragma unroll
            for (int e = 0; e < 6; ++e) lg[e] = fmaf(rv, w2[h * 6 + e], lg[e]);
        }
        float mx = lg[0];
#pragma unroll
        for (int e = 1; e < 6; ++e) mx = fmaxf(mx, lg[e]);
        float sum = 0.f;
#pragma unroll
        for (int e = 0; e < 6; ++e) { lg[e] = __expf(lg[e] - mx); sum += lg[e]; }
        float inv = 1.f / sum;
        int r = (b0 + tid) * 8 + s;
#pragma unroll
        for (int e = 0; e < 6; ++e) g_routing[r * 6 + e] = lg[e] * inv;
    }
}

// -------- fp8 GEMM chunk: pair-grouped commits, wait-at-top, 6-slot ring -----
// A [64][K] fp8 in smem (row stride lda bytes, ≡16 mod 128).
// B = WT rows [nc..nc+127][K] fp8; stage = k32 slice, smem rows stride 48 B.
#define LDA_X 528
#define LDA_H1 1040
#define WS_SLOT_B 6144    // 128 rows * 48 B

template <int MODE>
__device__ __forceinline__ void mma_chunk(
    const __nv_fp8_e4m3* __restrict__ Asm, int lda, int K,
    const __nv_fp8_e4m3* __restrict__ WT, int nc,   // WT: [N][K], rows n
    const char* __restrict__ ws, uint32_t ws_u32,
    const float* __restrict__ biasg,
    __nv_fp8_e4m3* __restrict__ h1out,
    const float* __restrict__ we3g, float (*s)[3])
{
    const int tid = threadIdx.x;
    const int lane = tid & 31, warp = tid >> 5;
    const int wr = warp >> 2, wc = warp & 3;
    const int rowbase = wr * 32, colbase = wc * 32;
    const int li = lane & 15, lj = lane >> 4;

    float c[2][4][4];
#pragma unroll
    for (int mt = 0; mt < 2; ++mt)
#pragma unroll
        for (int nt = 0; nt < 4; ++nt)
#pragma unroll
            for (int v = 0; v < 4; ++v) c[mt][nt][v] = 0.f;

    // cp.async: stage = 128 n-rows x 32 k-bytes; 1x16B per thread
    const int crow = tid >> 1;            // 0..127
    const int chalf = (tid & 1) * 16;
    const uint32_t dst0 = ws_u32 + (uint32_t)(crow * 48 + chalf);
    const __nv_fp8_e4m3* src0 = WT + (size_t)(nc + crow) * K + chalf;
    const int nst = K >> 5;               // 16 or 32
    const int niter = nst >> 1;

    // prologue: guard ws vs previous chunk readers; commit G0={0,1}, G1={2,3}
    __syncthreads();
    cp16(dst0 + 0u * WS_SLOT_B, src0);
    cp16(dst0 + 1u * WS_SLOT_B, src0 + 32);
    cp_commit();
    cp16(dst0 + 2u * WS_SLOT_B, src0 + 64);
    cp16(dst0 + 3u * WS_SLOT_B, src0 + 96);
    cp_commit();

    const __nv_fp8_e4m3* a0p = Asm + (size_t)(rowbase + li) * lda + lj * 16;
    const __nv_fp8_e4m3* a1p = a0p + (size_t)16 * lda;
    const uint32_t bq0 = ws_u32 + (uint32_t)((colbase + li) * 48 + lj * 16);
    const uint32_t bq1 = bq0 + 16 * 48;

    int sc = 0, sf = 4;
    for (int it = 0; it < niter; ++it) {
        if (it + 1 < niter) cp_wait1(); else cp_wait0();
        __syncthreads();

        if (2 * it + 4 < nst) {
            const __nv_fp8_e4m3* sg = src0 + (size_t)(2 * it + 4) * 32;
            cp16(dst0 + (uint32_t)sf * WS_SLOT_B, sg);
            cp16(dst0 + (uint32_t)(sf + 1) * WS_SLOT_B, sg + 32);
            cp_commit();
        }

#pragma unroll
        for (int half = 0; half < 2; ++half) {
            const int st = 2 * it + half;
            const int sl = sc + half;
            uint32_t a[2][4], b0[4], b1[4];
            ldsm_x4(a[0], smem_u32(a0p + st * 32));
            ldsm_x4(a[1], smem_u32(a1p + st * 32));
            ldsm_x4(b0, bq0 + (uint32_t)sl * WS_SLOT_B);   // n 0..15
            ldsm_x4(b1, bq1 + (uint32_t)sl * WS_SLOT_B);   // n 16..31
            // fragments: {r0,r2} = n-block lo (k0-15,k16-31), {r1,r3} = n-block hi
            mma_fp8(c[0][0], a[0], b0[0], b0[2]);
            mma_fp8(c[0][1], a[0], b0[1], b0[3]);
            mma_fp8(c[0][2], a[0], b1[0], b1[2]);
            mma_fp8(c[0][3], a[0], b1[1], b1[3]);
            mma_fp8(c[1][0], a[1], b0[0], b0[2]);
            mma_fp8(c[1][1], a[1], b0[1], b0[3]);
            mma_fp8(c[1][2], a[1], b1[0], b1[2]);
            mma_fp8(c[1][3], a[1], b1[1], b1[3]);
        }

        sc += 2; if (sc == 6) sc = 0;
        sf += 2; if (sf == 6) sf = 0;
    }

    // epilogue
#pragma unroll
    for (int mt = 0; mt < 2; ++mt) {
#pragma unroll
        for (int nt = 0; nt < 4; ++nt) {
            const int colc = colbase + nt * 8 + 2 * (lane & 3);
            float2 bb = *(const float2*)(biasg + colc);
            float t0 = fast_tanh(c[mt][nt][0] + bb.x);
            float t1 = fast_tanh(c[mt][nt][1] + bb.y);
            float t2 = fast_tanh(c[mt][nt][2] + bb.x);
            float t3 = fast_tanh(c[mt][nt][3] + bb.y);
            const int ra = rowbase + mt * 16 + (lane >> 2);
            if (MODE == 0) {
                __nv_fp8x2_e4m3 p0(make_float2(t0, t1));
                __nv_fp8x2_e4m3 p1(make_float2(t2, t3));
                *(__nv_fp8x2_e4m3*)&h1out[(size_t)ra * LDA_H1 + nc + colc] = p0;
                *(__nv_fp8x2_e4m3*)&h1out[(size_t)(ra + 8) * LDA_H1 + nc + colc] = p1;
            } else {
                const float* w3a = we3g + (size_t)(nc + colc) * 3;
#pragma unroll
                for (int o = 0; o < 3; ++o) {
                    float wa = w3a[o], wb2 = w3a[3 + o];
                    s[mt * 2 + 0][o] += t0 * wa + t1 * wb2;
                    s[mt * 2 + 1][o] += t2 * wa + t3 * wb2;
                }
            }
        }
    }
}

// -------- main kernel: grid (512 tiles, 6 experts) x 256 threads --------
// smem: xs 33792 | h1 66560 | ws 36864 => 137216
__global__ __launch_bounds__(256, 1) void moe_kernel(
    const float* __restrict__ x,
    const float* __restrict__ be1, const float* __restrict__ be2,
    const float* __restrict__ We3, const float* __restrict__ be3)
{
    extern __shared__ char smraw[];
    __nv_fp8_e4m3* xs  = (__nv_fp8_e4m3*)(smraw);
    __nv_fp8_e4m3* h1s = (__nv_fp8_e4m3*)(smraw + 33792);
    char*          ws  = smraw + 100352;

    const int tid = threadIdx.x;
    const int lane = tid & 31, warp = tid >> 5;
    const int wr = warp >> 2, wc = warp & 3;
    const int r0 = blockIdx.x * 64;
    const int e  = blockIdx.y;
    const uint32_t ws_u32 = smem_u32(ws);

    // x -> fp8 smem (row stride 528 B)
    for (int i = tid; i < 64 * 512 / 4; i += 256) {
        int row = i >> 7, c4 = i & 127;
        float4 v = *(const float4*)(x + (size_t)(r0 + row) * 512 + c4 * 4);
        __nv_fp8x4_e4m3 p(v);
        *(uint32_t*)&xs[(size_t)row * LDA_X + c4 * 4] = *(uint32_t*)&p;
    }
    // (xs ordered before first A-read by mma_chunk's prologue barriers)

    const __nv_fp8_e4m3* W1 = g_We1t + (size_t)e * 1024 * 512;
    const float* b1 = be1 + e * 1024;
    for (int nc = 0; nc < 1024; nc += 128)
        mma_chunk<0>(xs, LDA_X, 512, W1, nc, ws, ws_u32, b1 + nc,
                     h1s, nullptr, nullptr);
    __syncthreads();   // h1 complete before any warp reads it

    float s[4][3];
#pragma unroll
    for (int rt = 0; rt < 4; ++rt)
#pragma unroll
        for (int o = 0; o < 3; ++o) s[rt][o] = 0.f;

    const __nv_fp8_e4m3* W2 = g_We2t + (size_t)e * 512 * 1024;
    const float* b2 = be2 + e * 512;
    const float* w3 = We3 + (size_t)e * 1536;
    for (int nc = 0; nc < 512; nc += 128)
        mma_chunk<1>(h1s, LDA_H1, 1024, W2, nc, ws, ws_u32, b2 + nc,
                     nullptr, w3, s);

#pragma unroll
    for (int rt = 0; rt < 4; ++rt)
#pragma unroll
        for (int o = 0; o < 3; ++o) {
            s[rt][o] += __shfl_xor_sync(0xffffffffu, s[rt][o], 1);
            s[rt][o] += __shfl_xor_sync(0xffffffffu, s[rt][o], 2);
        }
    if ((lane & 3) == 0) {
        float bz[3];
#pragma unroll
        for (int o = 0; o < 3; ++o)
            bz[o] = (wc == 0) ? be3[e * 3 + o] : 0.f;
#pragma unroll
        for (int rt = 0; rt < 4; ++rt) {
            int row = wr * 32 + (rt >> 1) * 16 + (lane >> 2) + 8 * (rt & 1);
            float rw = g_routing[(size_t)(r0 + row) * 6 + e];
#pragma unroll
            for (int o = 0; o < 3; ++o)
                atomicAdd(&g_wacc[(size_t)(r0 + row) * 3 + o], rw * (s[rt][o] + bz[o]));
        }
    }
}

// -------- aggregator kernel --------
__global__ __launch_bounds__(256) void agg_kernel(
    const float* __restrict__ Wa1, const float* __restrict__ ba1,
    const float* __restrict__ Wa2, const float* __restrict__ ba2,
    float* __restrict__ out)
{
    int b = blockIdx.x * 256 + threadIdx.x;
    float f0 = 0.f, f1 = 0.f, f2 = 0.f;
#pragma unroll
    for (int i = 0; i < 8; ++i) {
        const float* w = &g_wacc[(size_t)(b * 8 + i) * 3];
        f0 += w[0]; f1 += w[1]; f2 += w[2];
    }
    f0 *= 0.125f; f1 *= 0.125f; f2 *= 0.125f;
    float a1[16];
#pragma unroll
    for (int j = 0; j < 16; ++j) {
        float v = ba1[j] + f0 * Wa1[j] + f1 * Wa1[16 + j] + f2 * Wa1[32 + j];
        a1[j] = fmaxf(v, 0.f);
    }
#pragma unroll
    for (int o = 0; o < 3; ++o) {
        float v = ba2[o];
#pragma unroll
        for (int j = 0; j < 16; ++j) v = fmaf(a1[j], Wa2[j * 3 + o], v);
        out[b * 3 + o] = v;
    }
}

// ---------------- launch ----------------
extern "C" void kernel_launch(void* const* d_in, const int* in_sizes, int n_in,
                              void* d_out, int out_size) {
    const float* x   = (const float*)d_in[0];
    const float* Wr1 = (const float*)d_in[1];
    const float* br1 = (const float*)d_in[2];
    const float* Wr2 = (const float*)d_in[3];
    const float* br2 = (const float*)d_in[4];
    const float* We1 = (const float*)d_in[5];
    const float* be1 = (const float*)d_in[6];
    const float* We2 = (const float*)d_in[7];
    const float* be2 = (const float*)d_in[8];
    const float* We3 = (const float*)d_in[9];
    const float* be3 = (const float*)d_in[10];
    const float* Wa1 = (const float*)d_in[11];
    const float* ba1 = (const float*)d_in[12];
    const float* Wa2 = (const float*)d_in[13];
    const float* ba2 = (const float*)d_in[14];
    float* out = (float*)d_out;

    const int SMEM_R = (64 * 512 + 512 * 32 + 64 * 32 + 192 + 32 + 8) * 4;
    const int SMEM_M = 137216;

    cudaFuncSetAttribute(routing_kernel, cudaFuncAttributeMaxDynamicSharedMemorySize, SMEM_R);
    cudaFuncSetAttribute(moe_kernel, cudaFuncAttributeMaxDynamicSharedMemorySize, SMEM_M);

    __nv_fp8_e4m3 *w1t, *w2t;
    cudaGetSymbolAddress((void**)&w1t, g_We1t);
    cudaGetSymbolAddress((void**)&w2t, g_We2t);

    transpose_kernel<<<dim3(16, 32, 6), dim3(32, 8)>>>(We1, w1t, 512, 1024);
    transpose_kernel<<<dim3(32, 16, 6), dim3(32, 8)>>>(We2, w2t, 1024, 512);
    routing_kernel<<<dim3(64, 8), 256, SMEM_R>>>(x, Wr1, br1, Wr2, br2);
    moe_kernel<<<dim3(512, 6), 256, SMEM_M>>>(x, be1, be2, We3, be3);
    agg_kernel<<<16, 256>>>(Wa1, ba1, Wa2, ba2, out);
}